// round 11
// baseline (speedup 1.0000x reference)
#include <cuda_runtime.h>
#include <cuda_fp16.h>
#include <math.h>

// Problem constants (validated against in_sizes at launch time)
#define NN 100000
#define NE 1600000
#define NF 64
#define NG 256

// ---------------- device scratch (static; no allocations) ----------------
__device__ int    g_anyodd_v11;             // dtype probe: nonzero odd word seen
__device__ int    g_ecnt_v11;               // atomic base for fused scan
__device__ int    g_degi_v11[NN];           // degree incl. self loop
__device__ float  g_dinv_v11[NN];           // rsqrt(deg)
__device__ int    g_rp_v11[NN];             // CSR range start (disjoint partition)
__device__ int    g_cursor_v11[NN];         // fill cursors
__device__ int    g_col_v11[NE];            // CSR column (src) indices
__device__ uint4  g_bufA_v11[NN * 8];       // fp16 messages: row = 8 uint4 = 64 halves
__device__ float4 g_bufB_v11[NN * 16];      // fp32 hidden state (row = 64 floats)
__device__ float  g_sums_v11[NG * 64];      // pooled sums
__device__ int    g_cnt_v11[NG];            // nodes per graph

// dtype-agnostic index load: int64 buffers have zero odd (high) words.
__device__ __forceinline__ int ld_idx(const void* p, int i, int is64) {
    if (is64) return (int)((const long long*)p)[i];
    return ((const int*)p)[i];
}
__device__ __forceinline__ int clampi(int v, int hi) {
    return v < 0 ? 0 : (v > hi ? hi : v);
}

// ---------------- kernels ----------------

// init scratch + dtype probe (any nonzero odd 32-bit word => int32 data)
__global__ void initdet_v11(const int* ei_words, int n) {
    int i = blockIdx.x * blockDim.x + threadIdx.x;
    if (i == 0) { g_anyodd_v11 = 0; g_ecnt_v11 = 0; }
    if (i < n) g_degi_v11[i] = 1;            // self loop contributes 1
    if (i < NG * 64) g_sums_v11[i] = 0.0f;
    if (i < NG) g_cnt_v11[i] = 0;
    if (i < 2048 && ei_words[2 * i + 1] != 0) atomicOr(&g_anyodd_v11, 1);
}

__global__ void count_v11(const void* ei, int E, int n) {
    int e = blockIdx.x * blockDim.x + threadIdx.x;
    if (e >= E) return;
    int is64 = (g_anyodd_v11 == 0);
    int d = clampi(ld_idx(ei, E + e, is64), n - 1);
    atomicAdd(&g_degi_v11[d], 1);
}

// Fused single-pass "scan": each 512-block scans its chunk of (deg-1), grabs a
// global base via atomicAdd (block order irrelevant — CSR ranges only need to
// be a disjoint partition of [0,E)), then writes rp/cursor/dinv.
__global__ void scanf_v11(int n) {
    __shared__ int wtot[17];
    __shared__ int base;
    int t = threadIdx.x;
    int i = blockIdx.x * 512 + t;
    int lane = t & 31;
    int w = t >> 5;

    if (t < 17) wtot[t] = 0;
    __syncthreads();

    int v = (i < n) ? (g_degi_v11[i] - 1) : 0;
    int s = v;
    #pragma unroll
    for (int off = 1; off < 32; off <<= 1) {
        int y = __shfl_up_sync(0xffffffffu, s, off);
        if (lane >= off) s += y;
    }
    if (lane == 31) wtot[w + 1] = s;
    __syncthreads();

    if (t == 0) {
        int acc = 0;
        #pragma unroll
        for (int k = 1; k <= 16; k++) { acc += wtot[k]; wtot[k] = acc; }
        base = atomicAdd(&g_ecnt_v11, acc);
    }
    __syncthreads();

    if (i < n) {
        int r = base + wtot[w] + (s - v);
        g_rp_v11[i] = r;
        g_cursor_v11[i] = r;
        g_dinv_v11[i] = rsqrtf((float)g_degi_v11[i]);
    }
}

__global__ void fill_v11(const void* ei, int E, int n) {
    int e = blockIdx.x * blockDim.x + threadIdx.x;
    if (e >= E) return;
    int is64 = (g_anyodd_v11 == 0);
    int s = clampi(ld_idx(ei, e, is64), n - 1);
    int d = clampi(ld_idx(ei, E + e, is64), n - 1);
    int pos = atomicAdd(&g_cursor_v11[d], 1);  // within node d's range
    g_col_v11[pos] = s;
}

// g_bufA[i,:] = half( (X[i,:] @ W) * dinv[i] ).  X = input if use_ext else bufB.
// One row per warp; W resident in smem as float2. fp32 compute, fp16 store.
__global__ void gemm_v11(const float* __restrict__ Xext, int use_ext,
                         const float* __restrict__ W, int n) {
    __shared__ float2 Ws[64 * 32];   // Ws[k*32+l] = {W[k][2l], W[k][2l+1]}
    for (int i = threadIdx.x; i < 64 * 32; i += blockDim.x)
        Ws[i] = ((const float2*)W)[i];
    __syncthreads();

    const float* X = use_ext ? Xext : (const float*)g_bufB_v11;

    int lane = threadIdx.x & 31;
    int row = (blockIdx.x * blockDim.x + threadIdx.x) >> 5;
    if (row >= n) return;

    const float* xr = X + row * 64;
    float ax = 0.f, ay = 0.f;
    #pragma unroll
    for (int k = 0; k < 64; k++) {
        float xv = xr[k];                  // broadcast load
        float2 w = Ws[k * 32 + lane];
        ax = fmaf(xv, w.x, ax);
        ay = fmaf(xv, w.y, ay);
    }
    float dv = g_dinv_v11[row];
    ((__half2*)g_bufA_v11)[row * 32 + lane] =
        __floats2half2_rn(ax * dv, ay * dv);   // 128B coalesced row store
}

// bufB[d,:] = relu( dinv[d] * (msg[d,:] + sum_{s in N(d)} msg[s,:]) + b )
// msg rows are fp16, 128B. Warp = node: 4 groups of 8 lanes, group g takes
// edges e≡g (mod 4); lane loads one uint4 (8 halves) of the row. fp32 accum;
// cross-group combine via shfl.xor(8|16).
__global__ void agg_v11(const float* __restrict__ bias, int n) {
    int node = (blockIdx.x * blockDim.x + threadIdx.x) >> 5;
    int lane = threadIdx.x & 31;
    if (node >= n) return;

    int grp = lane >> 3;        // 0..3: edge subset
    int c   = lane & 7;         // 16B chunk within 128B row

    int beg = g_rp_v11[node];
    int end = beg + g_degi_v11[node] - 1;   // deg-1 real edges

    float a0 = 0.f, a1 = 0.f, a2 = 0.f, a3 = 0.f;
    float a4 = 0.f, a5 = 0.f, a6 = 0.f, a7 = 0.f;

    if (grp == 0) {                          // self-loop term
        uint4 v = g_bufA_v11[node * 8 + c];
        float2 f0 = __half22float2(*(const __half2*)&v.x);
        float2 f1 = __half22float2(*(const __half2*)&v.y);
        float2 f2 = __half22float2(*(const __half2*)&v.z);
        float2 f3 = __half22float2(*(const __half2*)&v.w);
        a0 = f0.x; a1 = f0.y; a2 = f1.x; a3 = f1.y;
        a4 = f2.x; a5 = f2.y; a6 = f3.x; a7 = f3.y;
    }

    for (int e = beg + grp; e < end; e += 4) {
        int col = g_col_v11[e];
        uint4 v = g_bufA_v11[col * 8 + c];
        float2 f0 = __half22float2(*(const __half2*)&v.x);
        float2 f1 = __half22float2(*(const __half2*)&v.y);
        float2 f2 = __half22float2(*(const __half2*)&v.z);
        float2 f3 = __half22float2(*(const __half2*)&v.w);
        a0 += f0.x; a1 += f0.y; a2 += f1.x; a3 += f1.y;
        a4 += f2.x; a5 += f2.y; a6 += f3.x; a7 += f3.y;
    }

    // combine the 4 edge-groups (chunk c lives in lanes c, c+8, c+16, c+24)
    #pragma unroll
    for (int off = 8; off <= 16; off <<= 1) {
        a0 += __shfl_xor_sync(0xffffffffu, a0, off);
        a1 += __shfl_xor_sync(0xffffffffu, a1, off);
        a2 += __shfl_xor_sync(0xffffffffu, a2, off);
        a3 += __shfl_xor_sync(0xffffffffu, a3, off);
        a4 += __shfl_xor_sync(0xffffffffu, a4, off);
        a5 += __shfl_xor_sync(0xffffffffu, a5, off);
        a6 += __shfl_xor_sync(0xffffffffu, a6, off);
        a7 += __shfl_xor_sync(0xffffffffu, a7, off);
    }

    if (lane < 8) {                          // lane == c, grp 0
        float dv = g_dinv_v11[node];
        float4 b0 = ((const float4*)bias)[2 * c];
        float4 b1 = ((const float4*)bias)[2 * c + 1];
        float4 o0, o1;
        o0.x = fmaxf(fmaf(dv, a0, b0.x), 0.f);
        o0.y = fmaxf(fmaf(dv, a1, b0.y), 0.f);
        o0.z = fmaxf(fmaf(dv, a2, b0.z), 0.f);
        o0.w = fmaxf(fmaf(dv, a3, b0.w), 0.f);
        o1.x = fmaxf(fmaf(dv, a4, b1.x), 0.f);
        o1.y = fmaxf(fmaf(dv, a5, b1.y), 0.f);
        o1.z = fmaxf(fmaf(dv, a6, b1.z), 0.f);
        o1.w = fmaxf(fmaf(dv, a7, b1.w), 0.f);
        g_bufB_v11[node * 16 + 2 * c]     = o0;
        g_bufB_v11[node * 16 + 2 * c + 1] = o1;
    }
}

// sorted-batch segment-sum with local run accumulation over bufB (fp32).
#define PNODES 512
__global__ void pool_v11(const void* batch, int n) {
    int base = blockIdx.x * PNODES;
    int l  = threadIdx.x & 31;            // float2 lane (features 2l, 2l+1)
    int rg = threadIdx.x >> 5;            // 0..7
    int is64 = (g_anyodd_v11 == 0);
    const float2* B2 = (const float2*)g_bufB_v11;
    float ax = 0.f, ay = 0.f;
    int cur = -1, cnt = 0;
    for (int i = rg; i < PNODES; i += 8) {
        int node = base + i;
        if (node >= n) break;
        int g = clampi(ld_idx(batch, node, is64), NG - 1);
        if (g != cur) {
            if (cur >= 0) {
                atomicAdd(&g_sums_v11[cur * 64 + 2 * l], ax);
                atomicAdd(&g_sums_v11[cur * 64 + 2 * l + 1], ay);
                if (l == 0) atomicAdd(&g_cnt_v11[cur], cnt);
            }
            cur = g; ax = 0.f; ay = 0.f; cnt = 0;
        }
        float2 v = B2[node * 32 + l];
        ax += v.x; ay += v.y;
        cnt++;
    }
    if (cur >= 0) {
        atomicAdd(&g_sums_v11[cur * 64 + 2 * l], ax);
        atomicAdd(&g_sums_v11[cur * 64 + 2 * l + 1], ay);
        if (l == 0) atomicAdd(&g_cnt_v11[cur], cnt);
    }
}

__global__ void head_v11(const float* __restrict__ Wfc,
                         const float* __restrict__ bfc,
                         float* __restrict__ out) {
    int g = blockIdx.x * blockDim.x + threadIdx.x;
    if (g >= NG) return;
    float acc = 0.f;
    #pragma unroll
    for (int j = 0; j < 64; j++)
        acc = fmaf(g_sums_v11[g * 64 + j], Wfc[j], acc);
    float c = (float)g_cnt_v11[g];
    if (c < 1.0f) c = 1.0f;
    float z = acc / c + bfc[0];
    out[g] = 1.0f / (1.0f + expf(-z));
}

// ---------------- launch (kernel launches only; graph-capturable) ----------------
extern "C" void kernel_launch(void* const* d_in, const int* in_sizes, int n_in,
                              void* d_out, int out_size) {
    const float* x     = (const float*)d_in[0];
    const void*  ei    = d_in[1];
    const void*  batch = d_in[2];
    const float* W1    = (const float*)d_in[3];
    const float* b1    = (const float*)d_in[4];
    const float* W2    = (const float*)d_in[5];
    const float* b2    = (const float*)d_in[6];
    const float* Wfc   = (const float*)d_in[7];
    const float* bfc   = (const float*)d_in[8];
    float* out = (float*)d_out;

    int N = in_sizes[0] / NF;              // 100000
    int E = in_sizes[1] / 2;               // 1600000 (element count, dtype-independent)
    if (N > NN) N = NN;
    if (E > NE) E = NE;

    int nScan = (N + 511) / 512;           // 196
    int bEdge = (E + 255) / 256;
    int bNode = (N + 255) / 256;
    int bWarp = (N + 7) / 8;               // warp-per-node, 8 warps/block

    // --- init + dtype probe + graph structure (4 launches) ---
    initdet_v11<<<bNode, 256>>>((const int*)ei, N);
    count_v11<<<bEdge, 256>>>(ei, E, N);
    scanf_v11<<<nScan, 512>>>(N);
    fill_v11<<<bEdge, 256>>>(ei, E, N);

    // --- layer 1: x -> bufA(fp16) -> bufB(fp32) ---
    gemm_v11<<<bWarp, 256>>>(x, 1, W1, N);
    agg_v11<<<bWarp, 256>>>(b1, N);

    // --- layer 2: bufB -> bufA(fp16) -> bufB ---
    gemm_v11<<<bWarp, 256>>>(x, 0, W2, N);
    agg_v11<<<bWarp, 256>>>(b2, N);

    // --- pooling + head ---
    pool_v11<<<(N + PNODES - 1) / PNODES, 256>>>(batch, N);
    head_v11<<<1, 256>>>(Wfc, bfc, out);
}

// round 12
// speedup vs baseline: 1.3479x; 1.3479x over previous
#include <cuda_runtime.h>
#include <math.h>

// Problem constants (validated against in_sizes at launch time)
#define NN 100000
#define NE 1600000
#define NF 64
#define NG 256

typedef unsigned long long ull;

// ---------------- device scratch (static; no allocations) ----------------
__device__ int    g_anyodd_v12;             // dtype probe: nonzero odd word seen
__device__ int    g_ecnt_v12;               // atomic base for fused scan
__device__ int    g_degi_v12[NN];           // degree incl. self loop
__device__ float  g_dinv_v12[NN];           // rsqrt(deg)
__device__ int    g_rp_v12[NN];             // CSR range start (disjoint partition)
__device__ int    g_pos_v12[NE];            // per-edge slot within dst's range
__device__ int    g_col_v12[NE];            // CSR column (src) indices
__device__ float4 g_bufA_v12[NN * 16];      // fp32 messages (row = 64 floats)
__device__ float4 g_bufB_v12[NN * 16];      // fp32 hidden state
__device__ float  g_sums_v12[NG * 64];      // pooled sums
__device__ int    g_cnt_v12[NG];            // nodes per graph

// dtype-agnostic index load: int64 buffers have zero odd (high) words.
__device__ __forceinline__ int ld_idx(const void* p, int i, int is64) {
    if (is64) return (int)((const long long*)p)[i];
    return ((const int*)p)[i];
}
__device__ __forceinline__ int clampi(int v, int hi) {
    return v < 0 ? 0 : (v > hi ? hi : v);
}

// packed fp32x2 FMA: acc.{lo,hi} += x * w.{lo,hi}
__device__ __forceinline__ void fma2(ull& acc, float x, ull w) {
    ull a;
    asm("mov.b64 %0, {%1, %1};" : "=l"(a) : "f"(x));
    asm("fma.rn.f32x2 %0, %1, %2, %3;" : "=l"(acc) : "l"(a), "l"(w), "l"(acc));
}

// ---------------- kernels ----------------

// init scratch + dtype probe (any nonzero odd 32-bit word => int32 data)
__global__ void initdet_v12(const int* ei_words, int n) {
    int i = blockIdx.x * blockDim.x + threadIdx.x;
    if (i == 0) { g_anyodd_v12 = 0; g_ecnt_v12 = 0; }
    if (i < n) g_degi_v12[i] = 1;            // self loop contributes 1
    if (i < NG * 64) g_sums_v12[i] = 0.0f;
    if (i < NG) g_cnt_v12[i] = 0;
    if (i < 2048 && ei_words[2 * i + 1] != 0) atomicOr(&g_anyodd_v12, 1);
}

// degree count; atomic return value doubles as the edge's slot index.
__global__ void count_v12(const void* ei, int E, int n) {
    int e = blockIdx.x * blockDim.x + threadIdx.x;
    if (e >= E) return;
    int is64 = (g_anyodd_v12 == 0);
    int d = clampi(ld_idx(ei, E + e, is64), n - 1);
    g_pos_v12[e] = atomicAdd(&g_degi_v12[d], 1) - 1;   // 0-based among real edges
}

// Fused single-pass "scan": block scans its chunk of (deg-1), grabs a global
// base via atomicAdd (ranges only need to be a disjoint partition of [0,E)).
__global__ void scanf_v12(int n) {
    __shared__ int wtot[17];
    __shared__ int base;
    int t = threadIdx.x;
    int i = blockIdx.x * 512 + t;
    int lane = t & 31;
    int w = t >> 5;

    if (t < 17) wtot[t] = 0;
    __syncthreads();

    int v = (i < n) ? (g_degi_v12[i] - 1) : 0;
    int s = v;
    #pragma unroll
    for (int off = 1; off < 32; off <<= 1) {
        int y = __shfl_up_sync(0xffffffffu, s, off);
        if (lane >= off) s += y;
    }
    if (lane == 31) wtot[w + 1] = s;
    __syncthreads();

    if (t == 0) {
        int acc = 0;
        #pragma unroll
        for (int k = 1; k <= 16; k++) { acc += wtot[k]; wtot[k] = acc; }
        base = atomicAdd(&g_ecnt_v12, acc);
    }
    __syncthreads();

    if (i < n) {
        g_rp_v12[i] = base + wtot[w] + (s - v);
        g_dinv_v12[i] = rsqrtf((float)g_degi_v12[i]);
    }
}

// atomic-free fill: slot was captured in count.
__global__ void fill_v12(const void* ei, int E, int n) {
    int e = blockIdx.x * blockDim.x + threadIdx.x;
    if (e >= E) return;
    int is64 = (g_anyodd_v12 == 0);
    int s = clampi(ld_idx(ei, e, is64), n - 1);
    int d = clampi(ld_idx(ei, E + e, is64), n - 1);
    g_col_v12[g_rp_v12[d] + g_pos_v12[e]] = s;
}

// bufA[i,:] = (X[i,:] @ W) * dinv[i].  X = input if use_ext else bufB.
// Warp handles 8 rows; W staged in smem as paired-k ulonglong2 so one LDS.128
// feeds 4 k-steps; packed f32x2 FMA. Grid-stride over row-octets.
__global__ void gemm_v12(const float* __restrict__ Xext, int use_ext,
                         const float* __restrict__ W, int n) {
    __shared__ ulonglong2 Ws[32 * 32];
    // Ws[p*32+l] = { pair(W[2p][2l],W[2p][2l+1]), pair(W[2p+1][2l],W[2p+1][2l+1]) }
    for (int i = threadIdx.x; i < 1024; i += blockDim.x) {
        int p = i >> 5, l = i & 31;
        ull a = ((const ull*)W)[(2 * p) * 32 + l];
        ull b = ((const ull*)W)[(2 * p + 1) * 32 + l];
        Ws[i] = make_ulonglong2(a, b);
    }
    __syncthreads();

    const float* X = use_ext ? Xext : (const float*)g_bufB_v12;
    int lane = threadIdx.x & 31;
    int gw = (blockIdx.x * blockDim.x + threadIdx.x) >> 5;
    int nwarps = (gridDim.x * blockDim.x) >> 5;
    int nOct = (n + 7) >> 3;

    for (int oct = gw; oct < nOct; oct += nwarps) {
        int row0 = oct * 8;
        ull acc[8];
        #pragma unroll
        for (int r = 0; r < 8; r++) acc[r] = 0ull;   // bits of (0.f, 0.f)

        #pragma unroll 4
        for (int q = 0; q < 16; q++) {
            ulonglong2 w0 = Ws[(2 * q) * 32 + lane];     // k = 4q, 4q+1
            ulonglong2 w1 = Ws[(2 * q + 1) * 32 + lane]; // k = 4q+2, 4q+3
            #pragma unroll
            for (int r = 0; r < 8; r++) {
                int row = row0 + r; if (row > n - 1) row = n - 1;
                float4 xv = ((const float4*)(X + row * 64))[q];  // broadcast
                fma2(acc[r], xv.x, w0.x);
                fma2(acc[r], xv.y, w0.y);
                fma2(acc[r], xv.z, w1.x);
                fma2(acc[r], xv.w, w1.y);
            }
        }

        #pragma unroll
        for (int r = 0; r < 8; r++) {
            int row = row0 + r;
            if (row < n) {
                float lo, hi;
                asm("mov.b64 {%0, %1}, %2;" : "=f"(lo), "=f"(hi) : "l"(acc[r]));
                float dv = g_dinv_v12[row];
                ((float2*)g_bufA_v12)[row * 32 + lane] = make_float2(lo * dv, hi * dv);
            }
        }
    }
}

// bufB[d,:] = relu( dinv[d] * (msg[d,:] + sum_{s in N(d)} msg[s,:]) + b )
// fp32 messages. Warp = node; lanes 0-15 even edges, 16-31 odd edges; each
// lane gathers one float4 chunk of the 256B row. shfl.xor(16) combine.
__global__ void agg_v12(const float* __restrict__ bias, int n) {
    int node = (blockIdx.x * blockDim.x + threadIdx.x) >> 5;
    int lane = threadIdx.x & 31;
    if (node >= n) return;

    int half = lane >> 4;       // 0: even edges, 1: odd edges
    int c    = lane & 15;       // float4 chunk within row

    int beg = g_rp_v12[node];
    int end = beg + g_degi_v12[node] - 1;   // deg-1 real edges

    float4 acc;
    if (half == 0) {
        acc = g_bufA_v12[node * 16 + c];     // self-loop term (pre-scaled)
    } else {
        acc = make_float4(0.f, 0.f, 0.f, 0.f);
    }

    for (int e = beg + half; e < end; e += 2) {
        int col = g_col_v12[e];
        float4 v = g_bufA_v12[col * 16 + c];
        acc.x += v.x; acc.y += v.y; acc.z += v.z; acc.w += v.w;
    }

    acc.x += __shfl_xor_sync(0xffffffffu, acc.x, 16);
    acc.y += __shfl_xor_sync(0xffffffffu, acc.y, 16);
    acc.z += __shfl_xor_sync(0xffffffffu, acc.z, 16);
    acc.w += __shfl_xor_sync(0xffffffffu, acc.w, 16);

    if (half == 0) {
        float dv = g_dinv_v12[node];
        float4 bb = ((const float4*)bias)[c];
        float4 o;
        o.x = fmaxf(fmaf(dv, acc.x, bb.x), 0.f);
        o.y = fmaxf(fmaf(dv, acc.y, bb.y), 0.f);
        o.z = fmaxf(fmaf(dv, acc.z, bb.z), 0.f);
        o.w = fmaxf(fmaf(dv, acc.w, bb.w), 0.f);
        g_bufB_v12[node * 16 + c] = o;
    }
}

// sorted-batch segment-sum with local run accumulation over bufB (fp32).
#define PNODES 512
__global__ void pool_v12(const void* batch, int n) {
    int base = blockIdx.x * PNODES;
    int l  = threadIdx.x & 31;            // float2 lane (features 2l, 2l+1)
    int rg = threadIdx.x >> 5;            // 0..7
    int is64 = (g_anyodd_v12 == 0);
    const float2* B2 = (const float2*)g_bufB_v12;
    float ax = 0.f, ay = 0.f;
    int cur = -1, cnt = 0;
    for (int i = rg; i < PNODES; i += 8) {
        int node = base + i;
        if (node >= n) break;
        int g = clampi(ld_idx(batch, node, is64), NG - 1);
        if (g != cur) {
            if (cur >= 0) {
                atomicAdd(&g_sums_v12[cur * 64 + 2 * l], ax);
                atomicAdd(&g_sums_v12[cur * 64 + 2 * l + 1], ay);
                if (l == 0) atomicAdd(&g_cnt_v12[cur], cnt);
            }
            cur = g; ax = 0.f; ay = 0.f; cnt = 0;
        }
        float2 v = B2[node * 32 + l];
        ax += v.x; ay += v.y;
        cnt++;
    }
    if (cur >= 0) {
        atomicAdd(&g_sums_v12[cur * 64 + 2 * l], ax);
        atomicAdd(&g_sums_v12[cur * 64 + 2 * l + 1], ay);
        if (l == 0) atomicAdd(&g_cnt_v12[cur], cnt);
    }
}

__global__ void head_v12(const float* __restrict__ Wfc,
                         const float* __restrict__ bfc,
                         float* __restrict__ out) {
    int g = blockIdx.x * blockDim.x + threadIdx.x;
    if (g >= NG) return;
    float acc = 0.f;
    #pragma unroll
    for (int j = 0; j < 64; j++)
        acc = fmaf(g_sums_v12[g * 64 + j], Wfc[j], acc);
    float c = (float)g_cnt_v12[g];
    if (c < 1.0f) c = 1.0f;
    float z = acc / c + bfc[0];
    out[g] = 1.0f / (1.0f + expf(-z));
}

// ---------------- launch (kernel launches only; graph-capturable) ----------------
extern "C" void kernel_launch(void* const* d_in, const int* in_sizes, int n_in,
                              void* d_out, int out_size) {
    const float* x     = (const float*)d_in[0];
    const void*  ei    = d_in[1];
    const void*  batch = d_in[2];
    const float* W1    = (const float*)d_in[3];
    const float* b1    = (const float*)d_in[4];
    const float* W2    = (const float*)d_in[5];
    const float* b2    = (const float*)d_in[6];
    const float* Wfc   = (const float*)d_in[7];
    const float* bfc   = (const float*)d_in[8];
    float* out = (float*)d_out;

    int N = in_sizes[0] / NF;              // 100000
    int E = in_sizes[1] / 2;               // 1600000 (element count, dtype-independent)
    if (N > NN) N = NN;
    if (E > NE) E = NE;

    int nScan = (N + 511) / 512;           // 196
    int bEdge = (E + 255) / 256;
    int bNode = (N + 255) / 256;
    int bWarp = (N + 7) / 8;               // agg: warp-per-node, 8 warps/block
    int bGemm = 592;                       // grid-stride; 4 blocks/SM

    // Order chosen so the 4th launch (ncu's profiled slot) is gemm1.
    initdet_v12<<<bNode, 256>>>((const int*)ei, N);      // 0
    count_v12<<<bEdge, 256>>>(ei, E, N);                 // 1
    scanf_v12<<<nScan, 512>>>(N);                        // 2
    gemm_v12<<<bGemm, 256>>>(x, 1, W1, N);               // 3  <-- profiled
    fill_v12<<<bEdge, 256>>>(ei, E, N);                  // 4
    agg_v12<<<bWarp, 256>>>(b1, N);                      // 5

    gemm_v12<<<bGemm, 256>>>(x, 0, W2, N);               // 6
    agg_v12<<<bWarp, 256>>>(b2, N);                      // 7

    pool_v12<<<(N + PNODES - 1) / PNODES, 256>>>(batch, N);  // 8
    head_v12<<<1, 256>>>(Wfc, bfc, out);                 // 9
}

// round 14
// speedup vs baseline: 1.5419x; 1.1439x over previous
#include <cuda_runtime.h>
#include <math.h>

// Problem constants (validated against in_sizes at launch time)
#define NN 100000
#define NE 1600000
#define NF 64
#define NG 256

typedef unsigned long long ull;

// ---------------- device scratch (static; no allocations) ----------------
__device__ int    g_anyodd_v14;             // dtype probe: nonzero odd word seen
__device__ int    g_ecnt_v14;               // atomic base for fused scan
__device__ int    g_degi_v14[NN];           // degree incl. self loop
__device__ float  g_dinv_v14[NN];           // rsqrt(deg)
__device__ int    g_rp_v14[NN];             // CSR range start (disjoint partition)
__device__ int    g_pos_v14[NE];            // per-edge slot within dst's range
__device__ int    g_col_v14[NE];            // CSR column (src) indices
__device__ float4 g_bufA_v14[NN * 16];      // fp32 messages (row = 64 floats)
__device__ float4 g_bufB_v14[NN * 16];      // fp32 hidden state
__device__ float  g_sums_v14[NG * 64];      // pooled sums
__device__ int    g_cnt_v14[NG];            // nodes per graph

// dtype-agnostic index load: int64 buffers have zero odd (high) words.
__device__ __forceinline__ int ld_idx(const void* p, int i, int is64) {
    if (is64) return (int)((const long long*)p)[i];
    return ((const int*)p)[i];
}
__device__ __forceinline__ int clampi(int v, int hi) {
    return v < 0 ? 0 : (v > hi ? hi : v);
}

// packed fp32x2 FMA: acc.{lo,hi} += x * w.{lo,hi}
__device__ __forceinline__ void fma2(ull& acc, float x, ull w) {
    ull a;
    asm("mov.b64 %0, {%1, %1};" : "=l"(a) : "f"(x));
    asm("fma.rn.f32x2 %0, %1, %2, %3;" : "=l"(acc) : "l"(a), "l"(w), "l"(acc));
}

// ---------------- kernels ----------------

// init scratch + dtype probe (any nonzero odd 32-bit word => int32 data)
__global__ void initdet_v14(const int* ei_words, int n) {
    int i = blockIdx.x * blockDim.x + threadIdx.x;
    if (i == 0) { g_anyodd_v14 = 0; g_ecnt_v14 = 0; }
    if (i < n) g_degi_v14[i] = 1;            // self loop contributes 1
    if (i < NG * 64) g_sums_v14[i] = 0.0f;
    if (i < NG) g_cnt_v14[i] = 0;
    if (i < 2048 && ei_words[2 * i + 1] != 0) atomicOr(&g_anyodd_v14, 1);
}

// degree count; atomic return value doubles as the edge's slot index.
__global__ void count_v14(const void* ei, int E, int n) {
    int e = blockIdx.x * blockDim.x + threadIdx.x;
    if (e >= E) return;
    int is64 = (g_anyodd_v14 == 0);
    int d = clampi(ld_idx(ei, E + e, is64), n - 1);
    g_pos_v14[e] = atomicAdd(&g_degi_v14[d], 1) - 1;   // 0-based among real edges
}

// Fused single-pass "scan": block scans its chunk of (deg-1), grabs a global
// base via atomicAdd (ranges only need to be a disjoint partition of [0,E)).
__global__ void scanf_v14(int n) {
    __shared__ int wtot[17];
    __shared__ int base;
    int t = threadIdx.x;
    int i = blockIdx.x * 512 + t;
    int lane = t & 31;
    int w = t >> 5;

    if (t < 17) wtot[t] = 0;
    __syncthreads();

    int v = (i < n) ? (g_degi_v14[i] - 1) : 0;
    int s = v;
    #pragma unroll
    for (int off = 1; off < 32; off <<= 1) {
        int y = __shfl_up_sync(0xffffffffu, s, off);
        if (lane >= off) s += y;
    }
    if (lane == 31) wtot[w + 1] = s;
    __syncthreads();

    if (t == 0) {
        int acc = 0;
        #pragma unroll
        for (int k = 1; k <= 16; k++) { acc += wtot[k]; wtot[k] = acc; }
        base = atomicAdd(&g_ecnt_v14, acc);
    }
    __syncthreads();

    if (i < n) {
        g_rp_v14[i] = base + wtot[w] + (s - v);
        g_dinv_v14[i] = rsqrtf((float)g_degi_v14[i]);
    }
}

// atomic-free fill: slot was captured in count.
__global__ void fill_v14(const void* ei, int E, int n) {
    int e = blockIdx.x * blockDim.x + threadIdx.x;
    if (e >= E) return;
    int is64 = (g_anyodd_v14 == 0);
    int s = clampi(ld_idx(ei, e, is64), n - 1);
    int d = clampi(ld_idx(ei, E + e, is64), n - 1);
    g_col_v14[g_rp_v14[d] + g_pos_v14[e]] = s;
}

// bufA[i,:] = (X[i,:] @ W) * dinv[i].  X = input if use_ext else bufB.
// CTA = 128 threads = one 128-row tile. Phase 1: cooperative coalesced load of
// the 32KB X tile into smem (high MLP, streams at DRAM rate). Phase 2: compute
// from smem (LDS broadcasts, 29cyc) with paired-k W and packed f32x2 FMA.
__global__ void __launch_bounds__(128) gemm_v14(const float* __restrict__ Xext,
                                                int use_ext,
                                                const float* __restrict__ W, int n) {
    __shared__ ulonglong2 Ws[32 * 32];   // 16KB: W pairs (see v12 layout)
    __shared__ float4 Xs[128 * 16];      // 32KB: X tile, row-major float4

    int tid = threadIdx.x;               // 0..127
    int lane = tid & 31;
    int wid = tid >> 5;                  // 0..3
    int tile = blockIdx.x;
    const float* X = use_ext ? Xext : (const float*)g_bufB_v14;

    // stage W: Ws[p*32+l] = { pair(W[2p][2l],W[2p][2l+1]), pair(W[2p+1][2l],W[2p+1][2l+1]) }
    for (int i = tid; i < 1024; i += 128) {
        int p = i >> 5, l = i & 31;
        ull a = ((const ull*)W)[(2 * p) * 32 + l];
        ull b = ((const ull*)W)[(2 * p + 1) * 32 + l];
        Ws[i] = make_ulonglong2(a, b);
    }

    // stage X tile: 2048 float4, 16 per thread, coalesced; clamp row for tail tile
    #pragma unroll
    for (int j = 0; j < 16; j++) {
        int i = j * 128 + tid;           // tile-local float4 index
        int r = i >> 4;                  // tile-local row
        int c = i & 15;                  // float4 column
        int row = tile * 128 + r; if (row > n - 1) row = n - 1;
        Xs[i] = ((const float4*)(X + (size_t)row * 64))[c];
    }
    __syncthreads();

    // compute: warp handles rows [wid*32, wid*32+32), 8 rows at a time
    #pragma unroll
    for (int g = 0; g < 4; g++) {
        int r0 = wid * 32 + g * 8;       // tile-local first row of the octet
        ull acc[8];
        #pragma unroll
        for (int r = 0; r < 8; r++) acc[r] = 0ull;

        #pragma unroll 4
        for (int q = 0; q < 16; q++) {
            ulonglong2 w0 = Ws[(2 * q) * 32 + lane];     // k = 4q, 4q+1
            ulonglong2 w1 = Ws[(2 * q + 1) * 32 + lane]; // k = 4q+2, 4q+3
            #pragma unroll
            for (int r = 0; r < 8; r++) {
                float4 xv = Xs[(r0 + r) * 16 + q];       // smem broadcast
                fma2(acc[r], xv.x, w0.x);
                fma2(acc[r], xv.y, w0.y);
                fma2(acc[r], xv.z, w1.x);
                fma2(acc[r], xv.w, w1.y);
            }
        }

        #pragma unroll
        for (int r = 0; r < 8; r++) {
            int row = tile * 128 + r0 + r;
            if (row < n) {
                float lo, hi;
                asm("mov.b64 {%0, %1}, %2;" : "=f"(lo), "=f"(hi) : "l"(acc[r]));
                float dv = g_dinv_v14[row];
                ((float2*)g_bufA_v14)[row * 32 + lane] = make_float2(lo * dv, hi * dv);
            }
        }
    }
}

// bufB[d,:] = relu( dinv[d] * (msg[d,:] + sum_{s in N(d)} msg[s,:]) + b )
// fp32 messages. Warp = node; lanes 0-15 even edges, 16-31 odd edges; each
// lane gathers one float4 chunk of the 256B row. shfl.xor(16) combine.
__global__ void agg_v14(const float* __restrict__ bias, int n) {
    int node = (blockIdx.x * blockDim.x + threadIdx.x) >> 5;
    int lane = threadIdx.x & 31;
    if (node >= n) return;

    int half = lane >> 4;       // 0: even edges, 1: odd edges
    int c    = lane & 15;       // float4 chunk within row

    int beg = g_rp_v14[node];
    int end = beg + g_degi_v14[node] - 1;   // deg-1 real edges

    float4 acc;
    if (half == 0) {
        acc = g_bufA_v14[node * 16 + c];     // self-loop term (pre-scaled)
    } else {
        acc = make_float4(0.f, 0.f, 0.f, 0.f);
    }

    for (int e = beg + half; e < end; e += 2) {
        int col = g_col_v14[e];
        float4 v = g_bufA_v14[col * 16 + c];
        acc.x += v.x; acc.y += v.y; acc.z += v.z; acc.w += v.w;
    }

    acc.x += __shfl_xor_sync(0xffffffffu, acc.x, 16);
    acc.y += __shfl_xor_sync(0xffffffffu, acc.y, 16);
    acc.z += __shfl_xor_sync(0xffffffffu, acc.z, 16);
    acc.w += __shfl_xor_sync(0xffffffffu, acc.w, 16);

    if (half == 0) {
        float dv = g_dinv_v14[node];
        float4 bb = ((const float4*)bias)[c];
        float4 o;
        o.x = fmaxf(fmaf(dv, acc.x, bb.x), 0.f);
        o.y = fmaxf(fmaf(dv, acc.y, bb.y), 0.f);
        o.z = fmaxf(fmaf(dv, acc.z, bb.z), 0.f);
        o.w = fmaxf(fmaf(dv, acc.w, bb.w), 0.f);
        g_bufB_v14[node * 16 + c] = o;
    }
}

// sorted-batch segment-sum with local run accumulation over bufB (fp32).
#define PNODES 512
__global__ void pool_v14(const void* batch, int n) {
    int base = blockIdx.x * PNODES;
    int l  = threadIdx.x & 31;            // float2 lane (features 2l, 2l+1)
    int rg = threadIdx.x >> 5;            // 0..7
    int is64 = (g_anyodd_v14 == 0);
    const float2* B2 = (const float2*)g_bufB_v14;
    float ax = 0.f, ay = 0.f;
    int cur = -1, cnt = 0;
    for (int i = rg; i < PNODES; i += 8) {
        int node = base + i;
        if (node >= n) break;
        int g = clampi(ld_idx(batch, node, is64), NG - 1);
        if (g != cur) {
            if (cur >= 0) {
                atomicAdd(&g_sums_v14[cur * 64 + 2 * l], ax);
                atomicAdd(&g_sums_v14[cur * 64 + 2 * l + 1], ay);
                if (l == 0) atomicAdd(&g_cnt_v14[cur], cnt);
            }
            cur = g; ax = 0.f; ay = 0.f; cnt = 0;
        }
        float2 v = B2[node * 32 + l];
        ax += v.x; ay += v.y;
        cnt++;
    }
    if (cur >= 0) {
        atomicAdd(&g_sums_v14[cur * 64 + 2 * l], ax);
        atomicAdd(&g_sums_v14[cur * 64 + 2 * l + 1], ay);
        if (l == 0) atomicAdd(&g_cnt_v14[cur], cnt);
    }
}

__global__ void head_v14(const float* __restrict__ Wfc,
                         const float* __restrict__ bfc,
                         float* __restrict__ out) {
    int g = blockIdx.x * blockDim.x + threadIdx.x;
    if (g >= NG) return;
    float acc = 0.f;
    #pragma unroll
    for (int j = 0; j < 64; j++)
        acc = fmaf(g_sums_v14[g * 64 + j], Wfc[j], acc);
    float c = (float)g_cnt_v14[g];
    if (c < 1.0f) c = 1.0f;
    float z = acc / c + bfc[0];
    out[g] = 1.0f / (1.0f + expf(-z));
}

// ---------------- launch (kernel launches only; graph-capturable) ----------------
extern "C" void kernel_launch(void* const* d_in, const int* in_sizes, int n_in,
                              void* d_out, int out_size) {
    const float* x     = (const float*)d_in[0];
    const void*  ei    = d_in[1];
    const void*  batch = d_in[2];
    const float* W1    = (const float*)d_in[3];
    const float* b1    = (const float*)d_in[4];
    const float* W2    = (const float*)d_in[5];
    const float* b2    = (const float*)d_in[6];
    const float* Wfc   = (const float*)d_in[7];
    const float* bfc   = (const float*)d_in[8];
    float* out = (float*)d_out;

    int N = in_sizes[0] / NF;              // 100000
    int E = in_sizes[1] / 2;               // 1600000
    if (N > NN) N = NN;
    if (E > NE) E = NE;

    int nScan  = (N + 511) / 512;
    int bEdge  = (E + 255) / 256;
    int bNode  = (N + 255) / 256;
    int bWarp  = (N + 7) / 8;              // agg: warp-per-node, 8 warps/block
    int nTiles = (N + 127) / 128;          // 782

    // Order: 4th launch (profiled slot) = gemm layer 1.
    initdet_v14<<<bNode, 256>>>((const int*)ei, N);        // 0
    count_v14<<<bEdge, 256>>>(ei, E, N);                   // 1
    scanf_v14<<<nScan, 512>>>(N);                          // 2
    gemm_v14<<<nTiles, 128>>>(x, 1, W1, N);                // 3  <-- profiled
    fill_v14<<<bEdge, 256>>>(ei, E, N);                    // 4
    agg_v14<<<bWarp, 256>>>(b1, N);                        // 5

    gemm_v14<<<nTiles, 128>>>(x, 0, W2, N);                // 6
    agg_v14<<<bWarp, 256>>>(b2, N);                        // 7

    pool_v14<<<(N + PNODES - 1) / PNODES, 256>>>(batch, N);// 8
    head_v14<<<1, 256>>>(Wfc, bfc, out);                   // 9
}